// round 13
// baseline (speedup 1.0000x reference)
#include <cuda_runtime.h>
#include <cstdint>
#include <math.h>

#define Bn 8
#define Tn 2048
#define Cn 1024
#define Hn 64

// ---------------- device scratch (sanctioned no-alloc path) ----------------
__device__ float g_q[Bn * Tn * Hn];                 // h-PERMUTED within 8-blocks
__device__ float g_k[Bn * Tn * Hn];                 // h-PERMUTED within 8-blocks
__device__ float g_v[Bn * Tn * Hn];                 // V fp32 [b][t][h] (natural)
__device__ unsigned short g_vht[Bn * Hn * Tn];      // V bf16 hi, transposed [b][h][t]
__device__ unsigned short g_vlt[Bn * Hn * Tn];      // V bf16 lo, transposed
__device__ unsigned short g_wt_hi[3 * Hn * Cn];     // W bf16 hi, [o*64+n][k]
__device__ unsigned short g_wt_lo[3 * Hn * Cn];     // W bf16 lo

__device__ __forceinline__ float tf32_round(float x) {
    uint32_t u;
    asm("cvt.rna.tf32.f32 %0, %1;" : "=r"(u) : "f"(x));
    return __uint_as_float(u);
}
__device__ __forceinline__ uint32_t bfpack(float hi, float lo) {
    uint32_t d;
    asm("cvt.rn.bf16x2.f32 %0, %1, %2;" : "=r"(d) : "f"(hi), "f"(lo));
    return d;
}
__device__ __forceinline__ uint32_t smem_u32(const void* p) {
    uint32_t a;
    asm("{ .reg .u64 t; cvta.to.shared.u64 t, %1; cvt.u32.u64 %0, t; }" : "=r"(a) : "l"(p));
    return a;
}
__device__ __forceinline__ void cp16(uint32_t s, const void* g) {
    asm volatile("cp.async.cg.shared.global [%0], [%1], 16;" :: "r"(s), "l"(g));
}
#define CP_COMMIT() asm volatile("cp.async.commit_group;" ::: "memory")
#define CP_WAIT1()  asm volatile("cp.async.wait_group 1;" ::: "memory")
#define CP_WAIT0()  asm volatile("cp.async.wait_group 0;" ::: "memory")

__device__ __forceinline__ void mma_tf32(float* c, const uint32_t* a, const uint32_t* b) {
    asm volatile(
        "mma.sync.aligned.m16n8k8.row.col.f32.tf32.tf32.f32 "
        "{%0,%1,%2,%3}, {%4,%5,%6,%7}, {%8,%9}, {%0,%1,%2,%3};"
        : "+f"(c[0]), "+f"(c[1]), "+f"(c[2]), "+f"(c[3])
        : "r"(a[0]), "r"(a[1]), "r"(a[2]), "r"(a[3]), "r"(b[0]), "r"(b[1]));
}
__device__ __forceinline__ void mma_bf16(float* c, const uint32_t* a, const uint32_t* b) {
    asm volatile(
        "mma.sync.aligned.m16n8k16.row.col.f32.bf16.bf16.f32 "
        "{%0,%1,%2,%3}, {%4,%5,%6,%7}, {%8,%9}, {%0,%1,%2,%3};"
        : "+f"(c[0]), "+f"(c[1]), "+f"(c[2]), "+f"(c[3])
        : "r"(a[0]), "r"(a[1]), "r"(a[2]), "r"(a[3]), "r"(b[0]), "r"(b[1]));
}
__device__ __forceinline__ void ldm_x4(uint32_t& r0, uint32_t& r1, uint32_t& r2, uint32_t& r3,
                                       uint32_t addr) {
    asm volatile("ldmatrix.sync.aligned.m8n8.x4.shared.b16 {%0,%1,%2,%3}, [%4];"
        : "=r"(r0), "=r"(r1), "=r"(r2), "=r"(r3) : "r"(addr));
}

// h-permutation within 8-blocks: h = a + 4b (a:0..3, b:0..1) -> 2a + b
__device__ __forceinline__ int hperm(int h) {
    return (h & ~7) | (((h & 3) << 1) | ((h >> 2) & 1));
}

// ---------------------------------------------------------------------------
// prep: transpose weights to [o][n][k], bf16 Dekker split.
// ---------------------------------------------------------------------------
__global__ void prep_w(const float* __restrict__ Wk, const float* __restrict__ Wq,
                       const float* __restrict__ Wv) {
    int idx = blockIdx.x * 256 + threadIdx.x;
    int o = idx / (Hn * Cn);
    int rem = idx - o * (Hn * Cn);
    int n = rem / Cn;
    int k = rem - n * Cn;
    const float* W = (o == 0) ? Wq : (o == 1) ? Wk : Wv;
    float v = W[k * Hn + n];
    uint32_t p = bfpack(v, v);
    float fb = __uint_as_float(p & 0xFFFF0000u);
    uint32_t pl = bfpack(v - fb, v - fb);
    g_wt_hi[idx] = (unsigned short)(p >> 16);
    g_wt_lo[idx] = (unsigned short)(pl >> 16);
}

// ---------------------------------------------------------------------------
// V transpose + bf16 split (unchanged)
// ---------------------------------------------------------------------------
__global__ __launch_bounds__(128) void vt_split() {
    __shared__ float ts[64][65];
    const int b = blockIdx.y, t0 = blockIdx.x * 64;
    const int t = threadIdx.x;
    const float* vin = &g_v[((size_t)b * Tn + t0) * Hn];
    #pragma unroll
    for (int i = 0; i < 8; i++) {
        int c = t + i * 128;
        int r = c >> 4, c4 = (c & 15) * 4;
        float4 v = *(const float4*)&vin[r * Hn + c4];
        ts[r][c4] = v.x; ts[r][c4 + 1] = v.y; ts[r][c4 + 2] = v.z; ts[r][c4 + 3] = v.w;
    }
    __syncthreads();
    #pragma unroll
    for (int i = 0; i < 16; i++) {
        int c = t + i * 128;
        int h = c >> 5, c2 = (c & 31) * 2;
        float v0 = ts[c2][h], v1 = ts[c2 + 1][h];
        uint32_t ph = bfpack(v1, v0);
        float f0 = __uint_as_float(ph << 16);
        float f1 = __uint_as_float(ph & 0xFFFF0000u);
        uint32_t pl = bfpack(v1 - f1, v0 - f0);
        size_t o = (size_t)(b * Hn + h) * Tn + t0 + c2;
        *(uint32_t*)&g_vht[o] = ph;
        *(uint32_t*)&g_vlt[o] = pl;
    }
}

// ---------------------------------------------------------------------------
// QKV (R8 tiling) + ldmatrix B-frags + permuted q/k epilogue stores.
// ---------------------------------------------------------------------------
#define QAST 40
#define QKV_STAGE_B 51200
#define QKV_SMEM (2 * QKV_STAGE_B)

__global__ __launch_bounds__(256) void qkv_mma(
    const float* __restrict__ x,
    const float* __restrict__ bk, const float* __restrict__ bq, const float* __restrict__ bv)
{
    extern __shared__ char smc[];
    const uint32_t sb = smem_u32(smc);
    const int t = threadIdx.x;
    const int wid = t >> 5, lane = t & 31;
    const int wm = wid >> 2, wn = wid & 3;
    const int g = lane >> 2, tg = lane & 3;
    const int m0 = blockIdx.x * 128;

    // per-lane ldmatrix byte offset within a B nf-pair block (stride 20 u32)
    const int cB = ((8 * (lane >> 4) + (lane & 7)) * 20 + ((lane >> 3) & 1) * 4) * 4;

    float c[4][6][4];
    #pragma unroll
    for (int mf = 0; mf < 4; mf++)
        #pragma unroll
        for (int nf = 0; nf < 6; nf++)
            #pragma unroll
            for (int r = 0; r < 4; r++) c[mf][nf][r] = 0.0f;

    auto issue = [&](int ch, int st) {
        const int k0 = ch * 32;
        uint32_t sA = sb + (uint32_t)st * QKV_STAGE_B;
        uint32_t sBh = sA + 20480;
        uint32_t sBl = sBh + 15360;
        #pragma unroll
        for (int i = 0; i < 4; i++) {
            int cc = t + i * 256;
            int r = cc >> 3, o = cc & 7;
            cp16(sA + r * 160 + o * 16, &x[(size_t)(m0 + r) * Cn + k0 + o * 4]);
        }
        #pragma unroll
        for (int i = 0; i < 3; i++) {
            int cc = t + i * 256;
            int r = cc >> 2, o = cc & 3;
            cp16(sBh + r * 80 + o * 16,
                 (const char*)g_wt_hi + ((size_t)r * Cn + k0 + o * 8) * 2);
            cp16(sBl + r * 80 + o * 16,
                 (const char*)g_wt_lo + ((size_t)r * Cn + k0 + o * 8) * 2);
        }
    };

    issue(0, 0);
    CP_COMMIT();

    for (int ch = 0; ch < 32; ch++) {
        if (ch < 31) { issue(ch + 1, (ch + 1) & 1); CP_COMMIT(); CP_WAIT1(); }
        else         { CP_WAIT0(); }
        __syncthreads();

        char* stg = smc + (ch & 1) * QKV_STAGE_B;
        const float* As = (const float*)stg;
        const uint32_t stg_u = sb + (uint32_t)(ch & 1) * QKV_STAGE_B;
        const uint32_t sBh_u = stg_u + 20480;
        const uint32_t sBl_u = stg_u + 35840;

        #pragma unroll
        for (int ks = 0; ks < 2; ks++) {
            const int kk = ks * 16;
            uint32_t a_h[4][4], a_l[4][4], b_h[6][2], b_l[6][2];
            #pragma unroll
            for (int mf = 0; mf < 4; mf++) {
                int row = wm * 64 + mf * 16 + g;
                float2 p0 = *(const float2*)&As[row * QAST + kk + 2 * tg];
                float2 p1 = *(const float2*)&As[(row + 8) * QAST + kk + 2 * tg];
                float2 p2 = *(const float2*)&As[row * QAST + kk + 8 + 2 * tg];
                float2 p3 = *(const float2*)&As[(row + 8) * QAST + kk + 8 + 2 * tg];
                float2 ps[4] = {p0, p1, p2, p3};
                #pragma unroll
                for (int q = 0; q < 4; q++) {
                    uint32_t ph = bfpack(ps[q].y, ps[q].x);
                    a_h[mf][q] = ph;
                    float f0 = __uint_as_float(ph << 16);
                    float f1 = __uint_as_float(ph & 0xFFFF0000u);
                    a_l[mf][q] = bfpack(ps[q].y - f1, ps[q].x - f0);
                }
            }
            // B frags: 3 nf-pairs x {hi,lo} via ldmatrix.x4
            #pragma unroll
            for (int nfp = 0; nfp < 3; nfp++) {
                uint32_t blk = (uint32_t)((wn * 48 + nfp * 16) * 20 + ks * 8) * 4 + cB;
                ldm_x4(b_h[2 * nfp][0], b_h[2 * nfp][1],
                       b_h[2 * nfp + 1][0], b_h[2 * nfp + 1][1], sBh_u + blk);
                ldm_x4(b_l[2 * nfp][0], b_l[2 * nfp][1],
                       b_l[2 * nfp + 1][0], b_l[2 * nfp + 1][1], sBl_u + blk);
            }
            #pragma unroll
            for (int nf = 0; nf < 6; nf++)
                #pragma unroll
                for (int mf = 0; mf < 4; mf++)
                    mma_bf16(c[mf][nf], a_h[mf], b_h[nf]);
            #pragma unroll
            for (int nf = 0; nf < 6; nf++)
                #pragma unroll
                for (int mf = 0; mf < 4; mf++)
                    mma_bf16(c[mf][nf], a_h[mf], b_l[nf]);
            #pragma unroll
            for (int nf = 0; nf < 6; nf++)
                #pragma unroll
                for (int mf = 0; mf < 4; mf++)
                    mma_bf16(c[mf][nf], a_l[mf], b_h[nf]);
        }
        __syncthreads();
    }

    #pragma unroll
    for (int nf = 0; nf < 6; nf++) {
        int col = wn * 48 + nf * 8 + tg * 2;
        int o = col >> 6;
        int h = col & 63;
        const float* bias = (o == 0) ? bq : (o == 1) ? bk : bv;
        float2 bb = *(const float2*)&bias[h];
        #pragma unroll
        for (int mf = 0; mf < 4; mf++) {
            int r0 = m0 + wm * 64 + mf * 16 + g;
            float v00 = c[mf][nf][0] + bb.x, v01 = c[mf][nf][1] + bb.y;
            float v10 = c[mf][nf][2] + bb.x, v11 = c[mf][nf][3] + bb.y;
            if (o == 2) {
                *(float2*)&g_v[(size_t)r0 * Hn + h] = make_float2(v00, v01);
                *(float2*)&g_v[(size_t)(r0 + 8) * Hn + h] = make_float2(v10, v11);
            } else {
                float* gout = (o == 0) ? g_q : g_k;
                int p0 = hperm(h), p1 = hperm(h + 1);
                gout[(size_t)r0 * Hn + p0] = v00;
                gout[(size_t)r0 * Hn + p1] = v01;
                gout[(size_t)(r0 + 8) * Hn + p0] = v10;
                gout[(size_t)(r0 + 8) * Hn + p1] = v11;
            }
        }
    }
}

// ---------------------------------------------------------------------------
// Flash attention (R12 structure: 128 thr, balanced pairs, 128-wide chunks)
// + LDS.64 K-frags (h-permuted), float2 Q-frags, ldmatrix PV B-frags.
// ---------------------------------------------------------------------------
#define KST 68
#define VST 68
#define ATT_STAGE_B 69632
#define ATTN_SMEM (2 * ATT_STAGE_B)

__global__ __launch_bounds__(128) void attn_mma(float* __restrict__ out)
{
    extern __shared__ char smc[];
    const uint32_t sb = smem_u32(smc);

    const int t = threadIdx.x;
    const int w = t >> 5, lane = t & 31;
    const int g = lane >> 2, tg = lane & 3;
    const int b = blockIdx.y;
    const long base = (long)b * Tn * Hn;
    const float scale = 0.03125f;     // 1024^-0.5

    // per-lane ldmatrix byte offset within a V nf-pair block (stride VST u32)
    const int cV = ((8 * (lane >> 4) + (lane & 7)) * VST + ((lane >> 3) & 1) * 4) * 4;

    auto issue = [&](int kc, int st) {
        uint32_t sK = sb + (uint32_t)st * ATT_STAGE_B;
        uint32_t sVh = sK + 34816;
        uint32_t sVl = sVh + 17408;
        #pragma unroll
        for (int i = 0; i < 16; i++) {
            int r = (t >> 4) + i * 8;
            int c4 = (t & 15) * 4;
            cp16(sK + (r * KST + c4) * 4, &g_k[base + (long)(kc + r) * Hn + c4]);
        }
        #pragma unroll
        for (int i = 0; i < 8; i++) {
            int cc = t + i * 128;
            int h = cc >> 4, o = cc & 15;
            size_t go = ((size_t)(b * Hn + h) * Tn + kc + o * 8) * 2;
            cp16(sVh + (h * VST + o * 4) * 4, (const char*)g_vht + go);
            cp16(sVl + (h * VST + o * 4) * 4, (const char*)g_vlt + go);
        }
    };

    for (int tloop = 0; tloop < 2; tloop++) {
        const int qi = (tloop == 0) ? blockIdx.x : (31 - blockIdx.x);
        const int q0 = qi * 64;
        const int rw = w * 16 + g;
        const int nch = (qi + 2) >> 1;

        issue(0, 0);
        CP_COMMIT();

        uint32_t qa[8][4];
        {
            const float* qp = &g_q[base + (long)(q0 + rw) * Hn];
            #pragma unroll
            for (int ksi = 0; ksi < 8; ksi++) {
                float2 q0f = *(const float2*)&qp[ksi * 8 + 2 * tg];
                float2 q1f = *(const float2*)&qp[8 * Hn + ksi * 8 + 2 * tg];
                qa[ksi][0] = __float_as_uint(tf32_round(q0f.x * scale));
                qa[ksi][2] = __float_as_uint(tf32_round(q0f.y * scale));
                qa[ksi][1] = __float_as_uint(tf32_round(q1f.x * scale));
                qa[ksi][3] = __float_as_uint(tf32_round(q1f.y * scale));
            }
        }

        float m0 = -1e30f, m1 = -1e30f, l0 = 0.0f, l1 = 0.0f;
        float o[8][4];
        #pragma unroll
        for (int nf = 0; nf < 8; nf++)
            #pragma unroll
            for (int r = 0; r < 4; r++) o[nf][r] = 0.0f;

        for (int jj = 0; jj < nch; jj++) {
            if (jj + 1 < nch) { issue((jj + 1) * 128, (jj + 1) & 1); CP_COMMIT(); CP_WAIT1(); }
            else              { CP_WAIT0(); }
            __syncthreads();

            char* stg = smc + (jj & 1) * ATT_STAGE_B;
            const float* ksm = (const float*)stg;
            const uint32_t stg_u = sb + (uint32_t)(jj & 1) * ATT_STAGE_B;
            const uint32_t sVh_u = stg_u + 34816;
            const uint32_t sVl_u = stg_u + 52224;

            // ---- S = Qs . K^T over 128 columns (LDS.64 K-frags, h-permuted) ----
            float s[16][4];
            #pragma unroll
            for (int nf = 0; nf < 16; nf++)
                #pragma unroll
                for (int r = 0; r < 4; r++) s[nf][r] = 0.0f;

            #pragma unroll
            for (int ksi = 0; ksi < 8; ksi++) {
                #pragma unroll
                for (int nf = 0; nf < 16; nf++) {
                    float2 kf = *(const float2*)&ksm[(nf * 8 + g) * KST + ksi * 8 + 2 * tg];
                    uint32_t bf[2] = {__float_as_uint(kf.x), __float_as_uint(kf.y)};
                    mma_tf32(s[nf], qa[ksi], bf);
                }
            }

            // ---- causal mask (last chunk only) ----
            if (jj == nch - 1) {
                const int kc = jj * 128;
                const int rg0 = q0 + rw, rg1 = rg0 + 8;
                #pragma unroll
                for (int nf = 0; nf < 16; nf++) {
                    int col = kc + nf * 8 + 2 * tg;
                    if (col     > rg0) s[nf][0] = -1e30f;
                    if (col + 1 > rg0) s[nf][1] = -1e30f;
                    if (col     > rg1) s[nf][2] = -1e30f;
                    if (col + 1 > rg1) s[nf][3] = -1e30f;
                }
            }

            // ---- online softmax ----
            float mx0 = -1e30f, mx1 = -1e30f;
            #pragma unroll
            for (int nf = 0; nf < 16; nf++) {
                mx0 = fmaxf(mx0, fmaxf(s[nf][0], s[nf][1]));
                mx1 = fmaxf(mx1, fmaxf(s[nf][2], s[nf][3]));
            }
            #pragma unroll
            for (int off = 1; off <= 2; off <<= 1) {
                mx0 = fmaxf(mx0, __shfl_xor_sync(0xffffffffu, mx0, off));
                mx1 = fmaxf(mx1, __shfl_xor_sync(0xffffffffu, mx1, off));
            }
            float mn0 = fmaxf(m0, mx0), mn1 = fmaxf(m1, mx1);
            float rs0 = 0.0f, rs1 = 0.0f;
            #pragma unroll
            for (int nf = 0; nf < 16; nf++) {
                s[nf][0] = __expf(s[nf][0] - mn0);
                s[nf][1] = __expf(s[nf][1] - mn0);
                s[nf][2] = __expf(s[nf][2] - mn1);
                s[nf][3] = __expf(s[nf][3] - mn1);
                rs0 += s[nf][0] + s[nf][1];
                rs1 += s[nf][2] + s[nf][3];
            }
            #pragma unroll
            for (int off = 1; off <= 2; off <<= 1) {
                rs0 += __shfl_xor_sync(0xffffffffu, rs0, off);
                rs1 += __shfl_xor_sync(0xffffffffu, rs1, off);
            }
            float a0 = __expf(m0 - mn0), a1 = __expf(m1 - mn1);
            l0 = l0 * a0 + rs0; m0 = mn0;
            l1 = l1 * a1 + rs1; m1 = mn1;
            #pragma unroll
            for (int nf = 0; nf < 8; nf++) {
                o[nf][0] *= a0; o[nf][1] *= a0;
                o[nf][2] *= a1; o[nf][3] *= a1;
            }

            // ---- O += P . V (bf16 k16, 3 terms; ldmatrix B-frags) ----
            #pragma unroll
            for (int ksi = 0; ksi < 8; ksi++) {
                uint32_t ah[4], al[4];
                #pragma unroll
                for (int q = 0; q < 4; q++) {
                    int sn = 2 * ksi + (q >> 1);
                    int e = (q & 1) * 2;
                    float s0 = s[sn][e], s1 = s[sn][e + 1];
                    uint32_t ph = bfpack(s1, s0);
                    ah[q] = ph;
                    float f0 = __uint_as_float(ph << 16);
                    float f1 = __uint_as_float(ph & 0xFFFF0000u);
                    al[q] = bfpack(s1 - f1, s0 - f0);
                }
                uint32_t bh[8][2], bl[8][2];
                #pragma unroll
                for (int nfp = 0; nfp < 4; nfp++) {
                    uint32_t blk = (uint32_t)(nfp * 16 * VST + ksi * 8) * 4 + cV;
                    ldm_x4(bh[2 * nfp][0], bh[2 * nfp][1],
                           bh[2 * nfp + 1][0], bh[2 * nfp + 1][1], sVh_u + blk);
                    ldm_x4(bl[2 * nfp][0], bl[2 * nfp][1],
                           bl[2 * nfp + 1][0], bl[2 * nfp + 1][1], sVl_u + blk);
                }
                #pragma unroll
                for (int nf = 0; nf < 8; nf++)
                    mma_bf16(o[nf], ah, bh[nf]);
                #pragma unroll
                for (int nf = 0; nf < 8; nf++)
                    mma_bf16(o[nf], ah, bl[nf]);
                #pragma unroll
                for (int nf = 0; nf < 8; nf++)
                    mma_bf16(o[nf], al, bh[nf]);
            }
            __syncthreads();
        }

        float inv0 = 1.0f / l0, inv1 = 1.0f / l1;
        #pragma unroll
        for (int nf = 0; nf < 8; nf++) {
            int col = nf * 8 + 2 * tg;
            long r0 = base + (long)(q0 + rw) * Hn + col;
            *(float2*)&out[r0]          = make_float2(o[nf][0] * inv0, o[nf][1] * inv0);
            *(float2*)&out[r0 + 8 * Hn] = make_float2(o[nf][2] * inv1, o[nf][3] * inv1);
        }
    }
}

// ---------------------------------------------------------------------------
extern "C" void kernel_launch(void* const* d_in, const int* in_sizes, int n_in,
                              void* d_out, int out_size)
{
    const float* x  = (const float*)d_in[0];
    const float* Wk = (const float*)d_in[1];
    const float* bk = (const float*)d_in[2];
    const float* Wq = (const float*)d_in[3];
    const float* bq = (const float*)d_in[4];
    const float* Wv = (const float*)d_in[5];
    const float* bv = (const float*)d_in[6];
    float* out = (float*)d_out;

    prep_w<<<(3 * Hn * Cn) / 256, 256>>>(Wk, Wq, Wv);

    cudaFuncSetAttribute(qkv_mma, cudaFuncAttributeMaxDynamicSharedMemorySize, QKV_SMEM);
    qkv_mma<<<(Bn * Tn) / 128, 256, QKV_SMEM>>>(x, bk, bq, bv);

    vt_split<<<dim3(Tn / 64, Bn), 128>>>();

    cudaFuncSetAttribute(attn_mma, cudaFuncAttributeMaxDynamicSharedMemorySize, ATTN_SMEM);
    attn_mma<<<dim3(16, Bn), 128, ATTN_SMEM>>>(out);
}